// round 1
// baseline (speedup 1.0000x reference)
#include <cuda_runtime.h>
#include <math.h>

#define NB 16
#define NT 2048
#define ND 512
#define NC 20
#define KE 40
#define KH 20
#define FEPS 1e-5f

// ---------------- scratch (device globals; no allocs allowed) ----------------
__device__ int            g_idx[NB][4][KE];   // sets: 0=easy_act,1=easy_bkg,2=hard_act,3=hard_bkg
__device__ float          g_kl[NB][4];        // 0=pos_act,1=neg_act,2=pos_bkg,3=neg_bkg
__device__ double         g_distill_sum;
__device__ float          g_ortho;
__device__ float          g_med[NB], g_amax[NB];
__device__ unsigned char  g_abin[NB][NT];

// ---------------- helpers ----------------
__device__ __forceinline__ unsigned long long make_key(float v, int t) {
    // all scores are >= 0, so float bit pattern ordering == value ordering.
    // low 32 bits: (NT-1-t) so that descending sort breaks ties by LOWEST index
    // (matches jax.lax.top_k).
    return ((unsigned long long)__float_as_uint(v) << 32) | (unsigned)(NT - 1 - t);
}

// Descending bitonic sort of NT=2048 u64 keys in shared memory, blockDim=1024.
__device__ __forceinline__ void bitonic_desc(unsigned long long* k) {
    const int tid = threadIdx.x;
    for (int kk = 2; kk <= NT; kk <<= 1) {
        for (int j = kk >> 1; j > 0; j >>= 1) {
            __syncthreads();
#pragma unroll
            for (int s = 0; s < NT / 1024; ++s) {
                int i = tid + s * 1024;
                int ixj = i ^ j;
                if (ixj > i) {
                    unsigned long long a = k[i], b = k[ixj];
                    bool desc = ((i & kk) == 0);
                    if (desc ? (a < b) : (a > b)) { k[i] = b; k[ixj] = a; }
                }
            }
        }
    }
    __syncthreads();
}

__device__ __forceinline__ float warp_sum(float v) {
#pragma unroll
    for (int o = 16; o; o >>= 1) v += __shfl_down_sync(0xffffffffu, v, o);
    return v;
}

// ---------------- kernels ----------------
__global__ void k_init() { g_distill_sum = 0.0; }

// Per-batch: sort a -> amax, median; abin = (a > median)
__global__ void __launch_bounds__(1024) k_median(const float* __restrict__ attn) {
    __shared__ unsigned long long keys[NT];
    __shared__ float s_med;
    const int b = blockIdx.x, tid = threadIdx.x;
    float v0 = attn[b * NT + tid];
    float v1 = attn[b * NT + tid + 1024];
    keys[tid]        = make_key(v0, tid);
    keys[tid + 1024] = make_key(v1, tid + 1024);
    bitonic_desc(keys);
    if (tid == 0) {
        g_amax[b] = __uint_as_float((unsigned)(keys[0] >> 32));
        float m1 = __uint_as_float((unsigned)(keys[1023] >> 32));
        float m2 = __uint_as_float((unsigned)(keys[1024] >> 32));
        s_med = 0.5f * (m1 + m2);
        g_med[b] = s_med;
    }
    __syncthreads();
    g_abin[b][tid]        = (v0 > s_med) ? 1 : 0;
    g_abin[b][tid + 1024] = (v1 > s_med) ? 1 : 0;
}

// One block per (score_set, batch): build score array, sort, emit top-k indices.
__global__ void __launch_bounds__(1024) k_sortsel(const float* __restrict__ attn,
                                                  const float* __restrict__ dmask) {
    __shared__ unsigned long long keys[NT];
    const int s = blockIdx.x;   // 0..3
    const int b = blockIdx.y;
    const int tid = threadIdx.x;
    const float amax = g_amax[b];
    const unsigned char* ab = g_abin[b];

    for (int t = tid; t < NT; t += 1024) {
        float a = attn[b * NT + t];
        float v;
        if (s == 0) {
            v = a * dmask[b * NT + t];
        } else if (s == 1) {
            v = (amax - a) * dmask[b * NT + t];
        } else {
            int bm3 = (t - 3 >= 0) ? (int)ab[t - 3] : 0;
            int bm2 = (t - 2 >= 0) ? (int)ab[t - 2] : 0;
            int bm1 = (t - 1 >= 0) ? (int)ab[t - 1] : 0;
            int b0  = (int)ab[t];
            int bp1 = (t + 1 < NT) ? (int)ab[t + 1] : 0;
            int bp2 = (t + 2 < NT) ? (int)ab[t + 2] : 0;
            int bp3 = (t + 3 < NT) ? (int)ab[t + 3] : 0;
            if (s == 2) {
                int er3 = bm1 & b0 & bp1;                         // erosion w=3
                int er7 = er3 & bm3 & bm2 & bp2 & bp3;            // erosion w=7
                v = a * (float)(er3 & (er7 ^ 1));                 // inner
            } else {
                int dl3 = bm1 | b0 | bp1;                         // dilation w=3
                int dl7 = dl3 | bm3 | bm2 | bp2 | bp3;            // dilation w=7
                v = a * (float)(dl7 & (dl3 ^ 1));                 // outer
            }
        }
        keys[t] = make_key(v, t);
    }
    bitonic_desc(keys);
    const int K = (s < 2) ? KE : KH;
    if (tid < K) g_idx[b][s][tid] = (NT - 1) - (int)(unsigned)(keys[tid] & 0xffffffffu);
}

// One block per (combo, batch). 640 threads = 20 warps (one per hard row).
// q-side (40 rows: mu, 1/cov) staged in dynamic smem; p row in registers.
__global__ void __launch_bounds__(640) k_kl(const float* __restrict__ mu,
                                            const float* __restrict__ var) {
    extern __shared__ float sm[];
    float* mu_q = sm;                 // [KE][ND]
    float* r_q  = sm + KE * ND;       // [KE][ND]
    __shared__ float Lq[KE];
    __shared__ float wsum[20];

    const int combo = blockIdx.x;     // 0..3
    const int b = blockIdx.y;
    const int p_set = 2 + (combo >> 1);                       // 2,2,3,3
    const int q_set = (combo == 1 || combo == 2) ? 1 : 0;     // 0,1,1,0
    const int warp = threadIdx.x >> 5;                        // 0..19
    const int lane = threadIdx.x & 31;

    // stage q rows (2 rows per warp)
    for (int j = warp; j < KE; j += 20) {
        const int idx = g_idx[b][q_set][j];
        const float4* mrow = (const float4*)(mu  + ((size_t)b * NT + idx) * ND);
        const float4* vrow = (const float4*)(var + ((size_t)b * NT + idx) * ND);
        float lsum = 0.f;
#pragma unroll
        for (int it = 0; it < 4; ++it) {
            int f = lane + it * 32;
            float4 m4 = mrow[f];
            float4 v4 = vrow[f];
            v4.x += FEPS; v4.y += FEPS; v4.z += FEPS; v4.w += FEPS;
            float4 r4 = make_float4(1.f / v4.x, 1.f / v4.y, 1.f / v4.z, 1.f / v4.w);
            ((float4*)(mu_q + j * ND))[f] = m4;
            ((float4*)(r_q  + j * ND))[f] = r4;
            lsum += logf(v4.x) + logf(v4.y) + logf(v4.z) + logf(v4.w);
        }
        lsum = warp_sum(lsum);
        if (lane == 0) Lq[j] = lsum;  // sum log cov_q
    }

    // stage p row (warp i owns hard row i) in registers
    float4 mp[4], cp[4];
    float Lp;
    {
        const int idx = g_idx[b][p_set][warp];
        const float4* mrow = (const float4*)(mu  + ((size_t)b * NT + idx) * ND);
        const float4* vrow = (const float4*)(var + ((size_t)b * NT + idx) * ND);
        float lsum = 0.f;
#pragma unroll
        for (int it = 0; it < 4; ++it) {
            int f = lane + it * 32;
            mp[it] = mrow[f];
            float4 v4 = vrow[f];
            cp[it] = make_float4(v4.x + FEPS, v4.y + FEPS, v4.z + FEPS, v4.w + FEPS);
            lsum += logf(cp[it].x) + logf(cp[it].y) + logf(cp[it].z) + logf(cp[it].w);
        }
        lsum = warp_sum(lsum);
        Lp = __shfl_sync(0xffffffffu, lsum, 0);
    }
    __syncthreads();

    float acc_inv = 0.f;
    for (int j = 0; j < KE; ++j) {
        const float4* mq = (const float4*)(mu_q + j * ND);
        const float4* rq = (const float4*)(r_q  + j * ND);
        float acc = 0.f;
#pragma unroll
        for (int it = 0; it < 4; ++it) {
            int f = lane + it * 32;
            float4 m4 = mq[f], r4 = rq[f];
            float dx = m4.x - mp[it].x; acc += (dx * dx + cp[it].x) * r4.x;
            float dy = m4.y - mp[it].y; acc += (dy * dy + cp[it].y) * r4.y;
            float dz = m4.z - mp[it].z; acc += (dz * dz + cp[it].z) * r4.z;
            float dw = m4.w - mp[it].w; acc += (dw * dw + cp[it].w) * r4.w;
        }
        acc = warp_sum(acc);
        if (lane == 0) {
            // dist = term1+term3 (=0.5*acc) + 0.5*(L_q - L_p) - 0.5*D
            float dist = 0.5f * acc + 0.5f * (Lq[j] - Lp) - 0.5f * (float)ND;
            acc_inv += 1.f / (dist + 1.f);
        }
    }
    if (lane == 0) wsum[warp] = acc_inv;
    __syncthreads();
    if (threadIdx.x == 0) {
        float s = 0.f;
        for (int w = 0; w < 20; ++w) s += wsum[w];
        g_kl[b][combo] = s / (float)(KH * KE);
    }
}

// warp-per-row cosine similarity + global mean (double accumulation)
__global__ void __launch_bounds__(256) k_distill(const float* __restrict__ mu,
                                                 const float* __restrict__ mc) {
    const int lane = threadIdx.x & 31;
    const int wib  = threadIdx.x >> 5;                 // 0..7
    const int gw   = blockIdx.x * 8 + wib;
    const int nw   = gridDim.x * 8;
    double local = 0.0;
    for (int row = gw; row < NB * NT; row += nw) {
        const float4* a = (const float4*)(mu + (size_t)row * ND);
        const float4* c = (const float4*)(mc + (size_t)row * ND);
        float dot = 0.f, n1 = 0.f, n2 = 0.f;
#pragma unroll
        for (int it = 0; it < 4; ++it) {
            float4 x = a[lane + it * 32];
            float4 y = c[lane + it * 32];
            dot += x.x * y.x + x.y * y.y + x.z * y.z + x.w * y.w;
            n1  += x.x * x.x + x.y * x.y + x.z * x.z + x.w * x.w;
            n2  += y.x * y.x + y.y * y.y + y.z * y.z + y.w * y.w;
        }
#pragma unroll
        for (int o = 16; o; o >>= 1) {
            dot += __shfl_down_sync(0xffffffffu, dot, o);
            n1  += __shfl_down_sync(0xffffffffu, n1, o);
            n2  += __shfl_down_sync(0xffffffffu, n2, o);
        }
        if (lane == 0) {
            float sim = dot / (fmaxf(sqrtf(n1), 1e-12f) * fmaxf(sqrtf(n2), 1e-12f));
            local += (double)((sim + 1.f) * 0.5f);
        }
    }
    __shared__ double bs[8];
    if (lane == 0) bs[wib] = local;
    __syncthreads();
    if (threadIdx.x == 0) {
        double s = 0.0;
        for (int w = 0; w < 8; ++w) s += bs[w];
        atomicAdd(&g_distill_sum, s);
    }
}

// single block: Frobenius norm of (normalize(tf) @ normalize(tf)^T - I)
__global__ void __launch_bounds__(512) k_ortho(const float* __restrict__ tf) {
    __shared__ float e[NC * ND];     // 40 KB
    __shared__ float partial[16];
    const int tid = threadIdx.x;
    const int warp = tid >> 5, lane = tid & 31;   // 16 warps
    for (int i = tid; i < NC * ND; i += 512) e[i] = tf[i];
    __syncthreads();
    for (int r = warp; r < NC; r += 16) {
        float s = 0.f;
        for (int d = lane; d < ND; d += 32) { float v = e[r * ND + d]; s += v * v; }
        s = warp_sum(s);
        float inv = 1.f / fmaxf(sqrtf(__shfl_sync(0xffffffffu, s, 0)), 1e-12f);
        for (int d = lane; d < ND; d += 32) e[r * ND + d] *= inv;
    }
    __syncthreads();
    float acc = 0.f;
    for (int p = warp; p < NC * NC; p += 16) {
        int i = p / NC, j = p % NC;
        float s = 0.f;
        for (int d = lane; d < ND; d += 32) s += e[i * ND + d] * e[j * ND + d];
        s = warp_sum(s);
        if (lane == 0) {
            float m = s - ((i == j) ? 1.f : 0.f);
            acc += m * m;
        }
    }
    if (lane == 0) partial[warp] = acc;
    __syncthreads();
    if (tid == 0) {
        float s = 0.f;
        for (int w = 0; w < 16; ++w) s += partial[w];
        g_ortho = sqrtf(s);
    }
}

__global__ void k_final(float* __restrict__ out, int out_size) {
    if (threadIdx.x == 0 && blockIdx.x == 0) {
        float distill = -logf((float)(g_distill_sum / (double)(NB * NT)));
        float act = 0.f, bkg = 0.f;
        for (int b = 0; b < NB; ++b) {
            act += -(logf(g_kl[b][0]) + logf(1.f - g_kl[b][1]));
            bkg += -(logf(g_kl[b][2]) + logf(1.f - g_kl[b][3]));
        }
        act /= (float)NB;
        bkg /= (float)NB;
        float ortho = g_ortho;
        float total = distill + act + bkg + ortho;
        float vals[5] = {total, distill, act, bkg, ortho};
        for (int i = 0; i < out_size && i < 5; ++i) out[i] = vals[i];
    }
}

// ---------------- launch ----------------
extern "C" void kernel_launch(void* const* d_in, const int* in_sizes, int n_in,
                              void* d_out, int out_size) {
    const float* attn      = (const float*)d_in[0];
    const float* mu        = (const float*)d_in[1];
    const float* var       = (const float*)d_in[2];
    const float* mu_clip   = (const float*)d_in[3];
    const float* text_feat = (const float*)d_in[4];
    const float* dmask     = (const float*)d_in[5];
    float* out = (float*)d_out;

    const int kl_smem = 2 * KE * ND * (int)sizeof(float);   // 160 KB
    cudaFuncSetAttribute(k_kl, cudaFuncAttributeMaxDynamicSharedMemorySize, kl_smem);

    k_init<<<1, 1>>>();
    k_median<<<NB, 1024>>>(attn);
    k_sortsel<<<dim3(4, NB), 1024>>>(attn, dmask);
    k_kl<<<dim3(4, NB), 640, kl_smem>>>(mu, var);
    k_distill<<<2048, 256>>>(mu, mu_clip);
    k_ortho<<<1, 512>>>(text_feat);
    k_final<<<1, 32>>>(out, out_size);
}

// round 2
// speedup vs baseline: 1.1967x; 1.1967x over previous
#include <cuda_runtime.h>
#include <math.h>

#define NB 16
#define NT 2048
#define ND 512
#define NC 20
#define KE 40
#define KH 20
#define FEPS 1e-5f
#define LN2F 0.69314718055994531f

// ---------------- scratch ----------------
__device__ int            g_idx[NB][4][KE];   // 0=easy_act,1=easy_bkg,2=hard_act,3=hard_bkg
__device__ float          g_kl[NB][4];        // sums of 1/(dist+1); /800 at the end
__device__ double         g_distill_sum;
__device__ float          g_amax[NB];
__device__ unsigned char  g_abin[NB][NT];

// ---------------- helpers ----------------
__device__ __forceinline__ float warp_sum(float v) {
#pragma unroll
    for (int o = 16; o; o >>= 1) v += __shfl_down_sync(0xffffffffu, v, o);
    return v;
}
__device__ __forceinline__ float warp_max(float v) {
#pragma unroll
    for (int o = 16; o; o >>= 1) v = fmaxf(v, __shfl_down_sync(0xffffffffu, v, o));
    return v;
}
__device__ __forceinline__ unsigned long long pk2(float lo, float hi) {
    unsigned long long r;
    asm("mov.b64 %0, {%1, %2};" : "=l"(r) : "f"(lo), "f"(hi));
    return r;
}
__device__ __forceinline__ float2 upk2(unsigned long long v) {
    float2 f;
    asm("mov.b64 {%0, %1}, %2;" : "=f"(f.x), "=f"(f.y) : "l"(v));
    return f;
}
__device__ __forceinline__ unsigned long long ffma2(unsigned long long a,
                                                   unsigned long long b,
                                                   unsigned long long c) {
    unsigned long long d;
    asm("fma.rn.f32x2 %0, %1, %2, %3;" : "=l"(d) : "l"(a), "l"(b), "l"(c));
    return d;
}

// Descending radix select: bit pattern of the value at rank k (0-indexed, desc)
// among sc[0..n). All scores are >= 0 so bit order == value order.
// Requires n % blockDim.x == 0 (uniform warp trips for __match_any_sync).
__device__ unsigned radix_select_desc(const float* sc, int n, int k,
                                      unsigned* hist, unsigned* shc) {
    const int tid = threadIdx.x, nthr = blockDim.x;
    unsigned prefix = 0, pmask = 0;
#pragma unroll
    for (int level = 0; level < 4; ++level) {
        const int shift = 24 - 8 * level;
        for (int i = tid; i < 256; i += nthr) hist[i] = 0;
        __syncthreads();
        for (int i = tid; i < n; i += nthr) {
            unsigned u = __float_as_uint(sc[i]);
            bool ok = ((u & pmask) == prefix);
            unsigned d = ok ? ((u >> shift) & 255u) : 0x100u;
            unsigned mm = __match_any_sync(0xffffffffu, d);
            if (ok && ((tid & 31) == __ffs(mm) - 1))
                atomicAdd(&hist[d], (unsigned)__popc(mm));
        }
        __syncthreads();
        if (tid < 32) {
            const int l = tid;
            unsigned c[8]; unsigned lsum = 0;
#pragma unroll
            for (int i = 0; i < 8; ++i) { c[i] = hist[l * 8 + i]; lsum += c[i]; }
            unsigned v = lsum;
#pragma unroll
            for (int off = 1; off < 32; off <<= 1) {
                unsigned t = __shfl_down_sync(0xffffffffu, v, off);
                if (l + off < 32) v += t;
            }
            unsigned cum = v - lsum;          // elements in higher bins
            int found = -1; unsigned nk = 0;
#pragma unroll
            for (int i = 7; i >= 0; --i) {
                if (found < 0 && (unsigned)k >= cum && (unsigned)k < cum + c[i]) {
                    found = l * 8 + i; nk = (unsigned)k - cum;
                }
                cum += c[i];
            }
            if (found >= 0) { shc[0] = (unsigned)found; shc[1] = nk; }
        }
        __syncthreads();
        prefix |= shc[0] << shift;
        pmask  |= 0xFFu << shift;
        k = (int)shc[1];
        __syncthreads();
    }
    return prefix;
}

// ---------------- kernels ----------------
// Per batch: amax, exact median (ranks 1023/1024), abin; zero accumulators.
__global__ void __launch_bounds__(256) k_prep(const float* __restrict__ attn) {
    __shared__ float sa[NT];
    __shared__ unsigned hist[256];
    __shared__ unsigned shc[2];
    __shared__ float red[8];
    const int b = blockIdx.x, tid = threadIdx.x;
    float lmax = 0.f;
    for (int t = tid; t < NT; t += 256) {
        float v = attn[b * NT + t];
        sa[t] = v;
        lmax = fmaxf(lmax, v);
    }
    lmax = warp_max(lmax);
    if ((tid & 31) == 0) red[tid >> 5] = lmax;
    __syncthreads();
    if (tid == 0) {
        float m = red[0];
        for (int w = 1; w < 8; ++w) m = fmaxf(m, red[w]);
        g_amax[b] = m;
    }
    unsigned v1 = radix_select_desc(sa, NT, 1023, hist, shc);
    unsigned v2 = radix_select_desc(sa, NT, 1024, hist, shc);
    float med = 0.5f * (__uint_as_float(v1) + __uint_as_float(v2));
    for (int t = tid; t < NT; t += 256) g_abin[b][t] = (sa[t] > med) ? 1 : 0;
    if (tid < 4) g_kl[b][tid] = 0.f;
    if (b == 0 && tid == 0) g_distill_sum = 0.0;
}

// One block per (score_set, batch): radix-select top-K index set.
__global__ void __launch_bounds__(256) k_topk(const float* __restrict__ attn,
                                              const float* __restrict__ dmask) {
    __shared__ float ss[NT];
    __shared__ unsigned char sab[NT];
    __shared__ unsigned hist[256];
    __shared__ unsigned shc[2];
    __shared__ unsigned bm[NT / 32];
    __shared__ unsigned pfx[NT / 32];
    __shared__ int s_cnt;
    const int s = blockIdx.x, b = blockIdx.y, tid = threadIdx.x;
    const float amax = g_amax[b];
    if (s >= 2) {
        for (int t = tid; t < NT; t += 256) sab[t] = g_abin[b][t];
        __syncthreads();
    }
    for (int t = tid; t < NT; t += 256) {
        float a = attn[b * NT + t];
        float v;
        if (s == 0) v = a * dmask[b * NT + t];
        else if (s == 1) v = (amax - a) * dmask[b * NT + t];
        else {
            int bm3 = (t >= 3) ? (int)sab[t - 3] : 0;
            int bm2 = (t >= 2) ? (int)sab[t - 2] : 0;
            int bm1 = (t >= 1) ? (int)sab[t - 1] : 0;
            int b0  = (int)sab[t];
            int bp1 = (t + 1 < NT) ? (int)sab[t + 1] : 0;
            int bp2 = (t + 2 < NT) ? (int)sab[t + 2] : 0;
            int bp3 = (t + 3 < NT) ? (int)sab[t + 3] : 0;
            if (s == 2) {
                int er3 = bm1 & b0 & bp1;
                int er7 = er3 & bm3 & bm2 & bp2 & bp3;
                v = a * (float)(er3 & (er7 ^ 1));
            } else {
                int dl3 = bm1 | b0 | bp1;
                int dl7 = dl3 | bm3 | bm2 | bp2 | bp3;
                v = a * (float)(dl7 & (dl3 ^ 1));
            }
        }
        ss[t] = v;
    }
    if (tid == 0) s_cnt = 0;
    for (int i = tid; i < NT / 32; i += 256) bm[i] = 0;
    __syncthreads();
    const int K = (s < 2) ? KE : KH;
    unsigned vk = radix_select_desc(ss, NT, K - 1, hist, shc);
    const float fvk = __uint_as_float(vk);
    // collect: strictly-greater first (arbitrary order), ties by lowest index.
    for (int t = tid; t < NT; t += 256) {
        float v = ss[t];
        if (v > fvk) {
            int p = atomicAdd(&s_cnt, 1);
            g_idx[b][s][p] = t;
        } else if (v == fvk) {
            atomicOr(&bm[t >> 5], 1u << (t & 31));
        }
    }
    __syncthreads();
    if (tid < 32) {
        const int l = tid;
        unsigned p0 = __popc(bm[2 * l]), p1 = __popc(bm[2 * l + 1]);
        unsigned ls = p0 + p1, v = ls;
#pragma unroll
        for (int off = 1; off < 32; off <<= 1) {
            unsigned t2 = __shfl_up_sync(0xffffffffu, v, off);
            if (l >= off) v += t2;
        }
        unsigned excl = v - ls;
        pfx[2 * l] = excl;
        pfx[2 * l + 1] = excl + p0;
    }
    __syncthreads();
    const int base = s_cnt;
    const int m = K - base;
    for (int t = tid; t < NT; t += 256) {
        if (ss[t] == fvk) {
            int r = (int)(pfx[t >> 5] + __popc(bm[t >> 5] & ((1u << (t & 31)) - 1u)));
            if (r < m) g_idx[b][s][base + r] = t;
        }
    }
}

// grid (4, NB): blockIdx.x = qset*2 + qhalf. 320 threads = 10 warps.
// Each warp holds 4 p-rows (2 hard_act + 2 hard_bkg) in registers (u=mu^2+cov,
// w=-2mu packed f32x2); q half (20 rows r=1/cov, s=mu*r) staged in smem.
// dist = 0.5*(sum u*r + sum w*s) + Dq - 0.5*Lp - D/2, Dq = 0.5*(A_q + Lq).
__global__ void __launch_bounds__(320, 1) k_kl(const float* __restrict__ mu,
                                               const float* __restrict__ var) {
    extern __shared__ float sm[];
    float* r_q = sm;              // [20][ND]
    float* s_q = sm + 20 * ND;    // [20][ND]
    __shared__ float Dq[20];
    const int qs = blockIdx.x >> 1;
    const int qh = blockIdx.x & 1;
    const int b  = blockIdx.y;
    const int warp = threadIdx.x >> 5;   // 0..9
    const int lane = threadIdx.x & 31;

    // stage q (2 rows per warp)
    for (int j = warp; j < 20; j += 10) {
        const int idx = g_idx[b][qs][qh * 20 + j];
        const float4* mrow = (const float4*)(mu  + ((size_t)(b * NT + idx)) * ND);
        const float4* vrow = (const float4*)(var + ((size_t)(b * NT + idx)) * ND);
        float lsum = 0.f, asum = 0.f;
#pragma unroll
        for (int it = 0; it < 4; ++it) {
            int f = lane + it * 32;
            float4 m4 = mrow[f], v4 = vrow[f];
            v4.x += FEPS; v4.y += FEPS; v4.z += FEPS; v4.w += FEPS;
            float4 r4 = make_float4(1.f / v4.x, 1.f / v4.y, 1.f / v4.z, 1.f / v4.w);
            float4 s4 = make_float4(m4.x * r4.x, m4.y * r4.y, m4.z * r4.z, m4.w * r4.w);
            ((float4*)(r_q + j * ND))[f] = r4;
            ((float4*)(s_q + j * ND))[f] = s4;
            lsum += __log2f(v4.x) + __log2f(v4.y) + __log2f(v4.z) + __log2f(v4.w);
            asum += m4.x * s4.x + m4.y * s4.y + m4.z * s4.z + m4.w * s4.w;
        }
        float red = warp_sum(asum + LN2F * lsum);
        if (lane == 0) Dq[j] = 0.5f * red;
    }

    // stage p rows in registers
    unsigned long long up[4][8], wp[4][8];
    float halfLp[4];
#pragma unroll
    for (int rr = 0; rr < 4; ++rr) {
        const int pset = 2 + (rr >> 1);
        const int idx = g_idx[b][pset][warp * 2 + (rr & 1)];
        const float4* mrow = (const float4*)(mu  + ((size_t)(b * NT + idx)) * ND);
        const float4* vrow = (const float4*)(var + ((size_t)(b * NT + idx)) * ND);
        float lsum = 0.f;
#pragma unroll
        for (int it = 0; it < 4; ++it) {
            int f = lane + it * 32;
            float4 m4 = mrow[f], v4 = vrow[f];
            v4.x += FEPS; v4.y += FEPS; v4.z += FEPS; v4.w += FEPS;
            up[rr][2 * it]     = pk2(m4.x * m4.x + v4.x, m4.y * m4.y + v4.y);
            up[rr][2 * it + 1] = pk2(m4.z * m4.z + v4.z, m4.w * m4.w + v4.w);
            wp[rr][2 * it]     = pk2(-2.f * m4.x, -2.f * m4.y);
            wp[rr][2 * it + 1] = pk2(-2.f * m4.z, -2.f * m4.w);
            lsum += __log2f(v4.x) + __log2f(v4.y) + __log2f(v4.z) + __log2f(v4.w);
        }
        lsum = warp_sum(lsum);
        halfLp[rr] = 0.5f * LN2F * __shfl_sync(0xffffffffu, lsum, 0);
    }
    __syncthreads();

    float accinv[4] = {0.f, 0.f, 0.f, 0.f};
    for (int j = 0; j < 20; ++j) {
        const ulonglong2* rq2 = (const ulonglong2*)(r_q + j * ND);
        const ulonglong2* sq2 = (const ulonglong2*)(s_q + j * ND);
        unsigned long long au[4] = {0, 0, 0, 0}, aw[4] = {0, 0, 0, 0};
#pragma unroll
        for (int it = 0; it < 4; ++it) {
            ulonglong2 r2 = rq2[lane + it * 32];
            ulonglong2 s2 = sq2[lane + it * 32];
#pragma unroll
            for (int rr = 0; rr < 4; ++rr) {
                au[rr] = ffma2(up[rr][2 * it],     r2.x, au[rr]);
                au[rr] = ffma2(up[rr][2 * it + 1], r2.y, au[rr]);
                aw[rr] = ffma2(wp[rr][2 * it],     s2.x, aw[rr]);
                aw[rr] = ffma2(wp[rr][2 * it + 1], s2.y, aw[rr]);
            }
        }
#pragma unroll
        for (int rr = 0; rr < 4; ++rr) {
            float2 a2 = upk2(au[rr]), b2 = upk2(aw[rr]);
            float red = warp_sum(a2.x + a2.y + b2.x + b2.y);
            if (lane == 0) {
                float dist = 0.5f * red + Dq[j] - halfLp[rr] - 0.5f * (float)ND;
                accinv[rr] += 1.f / (dist + 1.f);
            }
        }
    }
    if (lane == 0) {
        const int c_act = qs;                  // 0: pos_act, 1: neg_act
        const int c_bkg = (qs == 0) ? 3 : 2;   // 3: neg_bkg, 2: pos_bkg
        atomicAdd(&g_kl[b][c_act], accinv[0] + accinv[1]);
        atomicAdd(&g_kl[b][c_bkg], accinv[2] + accinv[3]);
    }
}

// warp-per-row cosine similarity + global mean (double accumulation)
__global__ void __launch_bounds__(256) k_distill(const float* __restrict__ mu,
                                                 const float* __restrict__ mc) {
    const int lane = threadIdx.x & 31;
    const int wib  = threadIdx.x >> 5;
    const int gw   = blockIdx.x * 8 + wib;
    const int nw   = gridDim.x * 8;
    double local = 0.0;
    for (int row = gw; row < NB * NT; row += nw) {
        const float4* a = (const float4*)(mu + (size_t)row * ND);
        const float4* c = (const float4*)(mc + (size_t)row * ND);
        float dot = 0.f, n1 = 0.f, n2 = 0.f;
#pragma unroll
        for (int it = 0; it < 4; ++it) {
            float4 x = a[lane + it * 32];
            float4 y = c[lane + it * 32];
            dot += x.x * y.x + x.y * y.y + x.z * y.z + x.w * y.w;
            n1  += x.x * x.x + x.y * x.y + x.z * x.z + x.w * x.w;
            n2  += y.x * y.x + y.y * y.y + y.z * y.z + y.w * y.w;
        }
#pragma unroll
        for (int o = 16; o; o >>= 1) {
            dot += __shfl_down_sync(0xffffffffu, dot, o);
            n1  += __shfl_down_sync(0xffffffffu, n1, o);
            n2  += __shfl_down_sync(0xffffffffu, n2, o);
        }
        if (lane == 0) {
            float sim = dot / (fmaxf(sqrtf(n1), 1e-12f) * fmaxf(sqrtf(n2), 1e-12f));
            local += (double)((sim + 1.f) * 0.5f);
        }
    }
    __shared__ double bs[8];
    if (lane == 0) bs[wib] = local;
    __syncthreads();
    if (threadIdx.x == 0) {
        double s = 0.0;
        for (int w = 0; w < 8; ++w) s += bs[w];
        atomicAdd(&g_distill_sum, s);
    }
}

// single block: ortho (Frobenius norm) then final scalar assembly
__global__ void __launch_bounds__(512) k_fin(const float* __restrict__ tf,
                                             float* __restrict__ out, int out_size) {
    __shared__ float e[NC * ND];
    __shared__ float partial[16];
    const int tid = threadIdx.x;
    const int warp = tid >> 5, lane = tid & 31;
    for (int i = tid; i < NC * ND; i += 512) e[i] = tf[i];
    __syncthreads();
    for (int r = warp; r < NC; r += 16) {
        float s = 0.f;
        for (int d = lane; d < ND; d += 32) { float v = e[r * ND + d]; s += v * v; }
        s = warp_sum(s);
        float inv = 1.f / fmaxf(sqrtf(__shfl_sync(0xffffffffu, s, 0)), 1e-12f);
        for (int d = lane; d < ND; d += 32) e[r * ND + d] *= inv;
    }
    __syncthreads();
    float acc = 0.f;
    for (int p = warp; p < NC * NC; p += 16) {
        int i = p / NC, j = p % NC;
        float s = 0.f;
        for (int d = lane; d < ND; d += 32) s += e[i * ND + d] * e[j * ND + d];
        s = warp_sum(s);
        if (lane == 0) {
            float m = s - ((i == j) ? 1.f : 0.f);
            acc += m * m;
        }
    }
    if (lane == 0) partial[warp] = acc;
    __syncthreads();
    if (tid == 0) {
        float s = 0.f;
        for (int w = 0; w < 16; ++w) s += partial[w];
        float ortho = sqrtf(s);
        float distill = -logf((float)(g_distill_sum / (double)(NB * NT)));
        const float inv_pairs = 1.f / (float)(KH * KE);
        float act = 0.f, bkg = 0.f;
        for (int b = 0; b < NB; ++b) {
            act += -(logf(g_kl[b][0] * inv_pairs) + logf(1.f - g_kl[b][1] * inv_pairs));
            bkg += -(logf(g_kl[b][2] * inv_pairs) + logf(1.f - g_kl[b][3] * inv_pairs));
        }
        act /= (float)NB;
        bkg /= (float)NB;
        float total = distill + act + bkg + ortho;
        float vals[5] = {total, distill, act, bkg, ortho};
        for (int i = 0; i < out_size && i < 5; ++i) out[i] = vals[i];
    }
}

// ---------------- launch ----------------
extern "C" void kernel_launch(void* const* d_in, const int* in_sizes, int n_in,
                              void* d_out, int out_size) {
    const float* attn      = (const float*)d_in[0];
    const float* mu        = (const float*)d_in[1];
    const float* var       = (const float*)d_in[2];
    const float* mu_clip   = (const float*)d_in[3];
    const float* text_feat = (const float*)d_in[4];
    const float* dmask     = (const float*)d_in[5];
    float* out = (float*)d_out;

    const int kl_smem = 2 * 20 * ND * (int)sizeof(float);   // 80 KB
    cudaFuncSetAttribute(k_kl, cudaFuncAttributeMaxDynamicSharedMemorySize, kl_smem);

    k_prep<<<NB, 256>>>(attn);
    k_topk<<<dim3(4, NB), 256>>>(attn, dmask);
    k_kl<<<dim3(4, NB), 320, kl_smem>>>(mu, var);
    k_distill<<<2048, 256>>>(mu, mu_clip);
    k_fin<<<1, 512>>>(text_feat, out, out_size);
}